// round 14
// baseline (speedup 1.0000x reference)
#include <cuda_runtime.h>
#include <cfloat>

#define Bn 16
#define Cn 64
#define Nn 2048
#define On 64
#define Kn 20
#define CNT_TOT (16*2048*20)

// ---------------- scratch (static device globals; no runtime allocation) ----------------
__device__ float  g_D[(size_t)Bn*Nn*Nn];     // 256 MB neg_dist scratch
__device__ float  g_xx[Bn*Nn];               // squared norms
__device__ int    g_idx[Bn*Nn*Kn];           // top-K index sets (order arbitrary)
__device__ float  g_U[(size_t)Bn*Nn*On];     // U[b][m][o] = Wd . x  (o contiguous)
__device__ float  g_Bse[(size_t)Bn*Nn*On];   // (V-U)[b][n][o]
__device__ double g_sum[On], g_sumsq[On];
__device__ float  g_scale[On], g_shift[On];

// ---------------- kernel 0: zero the stats accumulators (graph replays!) ----------------
__global__ void k_zero() {
    int o = threadIdx.x;
    g_sum[o] = 0.0; g_sumsq[o] = 0.0;
}

// ---------------- kernel 1: xx[b,n] = sum_c x^2 ----------------
__global__ void k_xx(const float* __restrict__ x) {
    int id = blockIdx.x * blockDim.x + threadIdx.x;   // 0 .. B*N-1
    if (id >= Bn * Nn) return;
    int b = id / Nn, n = id % Nn;
    const float* xp = x + (size_t)b * Cn * Nn + n;
    float s = 0.f;
#pragma unroll
    for (int c = 0; c < Cn; c++) {
        float v = xp[(size_t)c * Nn];
        s = fmaf(v, v, s);
    }
    g_xx[id] = s;
}

// ---------------- kernel 2: neg_dist 128x128 tiles, 8x8 per thread ----------------
// Triangular grid (tm >= tn); mirror written via smem transpose.
__global__ void __launch_bounds__(256) k_gram(const float* __restrict__ x) {
    __shared__ __align__(16) float sh[64 * 132];   // As|Bs during compute, Ts after

    int t = blockIdx.x, b = blockIdx.y;
    int tm = (int)((sqrtf(8.f * t + 1.f) - 1.f) * 0.5f);
    while ((tm + 1) * (tm + 2) / 2 <= t) tm++;
    while (tm * (tm + 1) / 2 > t) tm--;
    int tn = t - tm * (tm + 1) / 2;

    int n0 = tn * 128, m0 = tm * 128;
    const float* xb = x + (size_t)b * Cn * Nn;
    int tid = threadIdx.x, tx = tid & 15, ty = tid >> 4;

    float* As = sh;            // [32][128]
    float* Bs = sh + 32 * 128; // [32][128]

    float acc[8][8] = {};

    for (int kc = 0; kc < 64; kc += 32) {
        __syncthreads();
#pragma unroll
        for (int i = 0; i < 4; i++) {
            int f = tid + 256 * i;          // float4 index over 1024
            int c = f >> 5, c4 = (f & 31) * 4;
            *(float4*)&As[c * 128 + c4] = *(const float4*)&xb[(size_t)(kc + c) * Nn + n0 + c4];
            *(float4*)&Bs[c * 128 + c4] = *(const float4*)&xb[(size_t)(kc + c) * Nn + m0 + c4];
        }
        __syncthreads();
#pragma unroll 4
        for (int c = 0; c < 32; c++) {
            float4 a0 = *(float4*)&As[c * 128 + ty * 4];
            float4 a1 = *(float4*)&As[c * 128 + 64 + ty * 4];
            float4 b0 = *(float4*)&Bs[c * 128 + tx * 4];
            float4 b1 = *(float4*)&Bs[c * 128 + 64 + tx * 4];
            float av[8] = {a0.x, a0.y, a0.z, a0.w, a1.x, a1.y, a1.z, a1.w};
            float bv[8] = {b0.x, b0.y, b0.z, b0.w, b1.x, b1.y, b1.z, b1.w};
#pragma unroll
            for (int i = 0; i < 8; i++)
#pragma unroll
                for (int j = 0; j < 8; j++)
                    acc[i][j] = fmaf(av[i], bv[j], acc[i][j]);
        }
    }

    float xn[8], xm[8];
#pragma unroll
    for (int i = 0; i < 4; i++) {
        xn[i]     = g_xx[b * Nn + n0 + ty * 4 + i];
        xn[4 + i] = g_xx[b * Nn + n0 + 64 + ty * 4 + i];
        xm[i]     = g_xx[b * Nn + m0 + tx * 4 + i];
        xm[4 + i] = g_xx[b * Nn + m0 + 64 + tx * 4 + i];
    }

    float vv[8][8];
#pragma unroll
    for (int i = 0; i < 8; i++)
#pragma unroll
        for (int j = 0; j < 8; j++)
            vv[i][j] = 2.f * acc[i][j] - xn[i] - xm[j];

    float* Db = g_D + (size_t)b * Nn * Nn;

    // direct store: D[n][m]
#pragma unroll
    for (int i = 0; i < 8; i++) {
        int nl = (i < 4) ? (ty * 4 + i) : (64 + ty * 4 + i - 4);
        *(float4*)&Db[(size_t)(n0 + nl) * Nn + m0 + tx * 4] =
            make_float4(vv[i][0], vv[i][1], vv[i][2], vv[i][3]);
        *(float4*)&Db[(size_t)(n0 + nl) * Nn + m0 + 64 + tx * 4] =
            make_float4(vv[i][4], vv[i][5], vv[i][6], vv[i][7]);
    }

    // mirror store: D[m][n] via smem transpose (two 64-col halves)
    if (tm != tn) {
        float* Ts = sh;                       // [64][132]
#pragma unroll
        for (int h = 0; h < 2; h++) {
            __syncthreads();
#pragma unroll
            for (int i = 0; i < 8; i++) {
                int nl = (i < 4) ? (ty * 4 + i) : (64 + ty * 4 + i - 4);
#pragma unroll
                for (int j = 0; j < 4; j++)
                    Ts[(tx * 4 + j) * 132 + nl] = vv[i][h * 4 + j];
            }
            __syncthreads();
#pragma unroll
            for (int q = 0; q < 8; q++) {
                int f = tid + 256 * q;        // over 64*32 float4
                int mc = f >> 5, n4 = (f & 31) * 4;
                float4 w = *(float4*)&Ts[mc * 132 + n4];
                *(float4*)&Db[(size_t)(m0 + h * 64 + mc) * Nn + n0 + n4] = w;
            }
        }
    }
}

// ---------------- kernel 3: top-K=20, TWO rows per block, MLP-4 loads ----------------
// Per row: sampled threshold (min over warps of warp-max of one sample) ->
// ~170 candidates; sparse 256-bin histogram over [thr, 0]; suffix scan; direct
// emit of bins above the threshold bin (only the SET matters downstream);
// exact (value desc, idx asc) rank in the threshold bin -> identical set to
// stable top_k. Degenerate rows fall back to exact iterative argmax with
// block-uniform guards (no divergent barriers). f[r][i] = element tid*8+i of
// row rbase+r.
__global__ void __launch_bounds__(256) k_topk2() {
    int rbase = blockIdx.x * 2;                 // rows rbase, rbase+1
    int tid = threadIdx.x, lane = tid & 31, warp = tid >> 5;

    __shared__ float s_wmax[2][8];
    __shared__ int   hist[2][257];              // suffix-scanned in place
    __shared__ int   s_c[2], s_win[2], s_kp[2], s_cnt[2], s_tb[2];
    __shared__ float          cv[2][64];
    __shared__ unsigned short cix[2][64];
    __shared__ float sv[8];
    __shared__ int   si[8];
    __shared__ int   swin;

    const float4* dA = (const float4*)(g_D + (size_t)rbase * Nn);
    const float4* dB = (const float4*)(g_D + (size_t)(rbase + 1) * Nn);
    // 4 independent loads, front-batched (MLP 4)
    float4 A0 = dA[tid * 2], A1 = dA[tid * 2 + 1];
    float4 B0 = dB[tid * 2], B1 = dB[tid * 2 + 1];

    float f[2][8] = {{A0.x, A0.y, A0.z, A0.w, A1.x, A1.y, A1.z, A1.w},
                     {B0.x, B0.y, B0.z, B0.w, B1.x, B1.y, B1.z, B1.w}};

    // sampled thresholds (both rows)
    float s0 = f[0][0], s1 = f[1][0];
#pragma unroll
    for (int off = 16; off; off >>= 1) {
        s0 = fmaxf(s0, __shfl_xor_sync(0xffffffffu, s0, off));
        s1 = fmaxf(s1, __shfl_xor_sync(0xffffffffu, s1, off));
    }
    if (lane == 0) { s_wmax[0][warp] = s0; s_wmax[1][warp] = s1; }
    hist[0][tid] = 0; hist[1][tid] = 0;
    if (tid == 0) {
        hist[0][256] = 0; hist[1][256] = 0;
        s_c[0] = s_c[1] = 0; s_cnt[0] = s_cnt[1] = 0; s_tb[0] = s_tb[1] = 0;
    }
    __syncthreads();

    float thr[2]; bool fb[2]; float scl[2];
#pragma unroll
    for (int r = 0; r < 2; r++) {
        float t = s_wmax[r][0];
#pragma unroll
        for (int w = 1; w < 8; w++) t = fminf(t, s_wmax[r][w]);
        thr[r] = t;
        fb[r] = (t > -1e-20f);                  // degenerate: many ~zero dists
        scl[r] = fb[r] ? 0.f : 255.f / (-t);
    }

    int bin[2][8];
#pragma unroll
    for (int r = 0; r < 2; r++) {
        if (!fb[r]) {
            int c = 0;
#pragma unroll
            for (int i = 0; i < 8; i++) {
                if (f[r][i] >= thr[r]) {
                    c++;
                    int bb = (int)((f[r][i] - thr[r]) * scl[r]);
                    bb = bb > 255 ? 255 : bb;
                    bin[r][i] = bb;
                    atomicAdd(&hist[r][bb], 1);
                } else bin[r][i] = -1;
            }
            c = __reduce_add_sync(0xffffffffu, c);
            if (lane == 0 && c) atomicAdd(&s_c[r], c);
        }
    }
    __syncthreads();

    bool ok[2];
#pragma unroll
    for (int r = 0; r < 2; r++) ok[r] = (!fb[r] && s_c[r] >= Kn);

    // suffix counts in place: warp r scans hist[r] (r = 0,1 in parallel)
    if (warp < 2 && ok[warp]) {
        int* h = hist[warp];
        int base = lane * 8, l[8], run = 0;
#pragma unroll
        for (int j = 7; j >= 0; j--) { run += h[base + j]; l[j] = run; }
        int tot = run, inc = tot;
#pragma unroll
        for (int off = 1; off < 32; off <<= 1) {
            int v = __shfl_down_sync(0xffffffffu, inc, off);
            if (lane + off < 32) inc += v;
        }
        int above = inc - tot;
#pragma unroll
        for (int j = 0; j < 8; j++) h[base + j] = l[j] + above;
    }
    __syncthreads();

#pragma unroll
    for (int r = 0; r < 2; r++) {
        if (ok[r]) {
            int cg = hist[r][tid], cgn = hist[r][tid + 1];
            if (cg >= Kn && cgn < Kn) { s_win[r] = tid; s_kp[r] = Kn - cgn; }
        }
    }
    __syncthreads();

    bool sel[2]; int win[2], kp[2];
#pragma unroll
    for (int r = 0; r < 2; r++) {
        if (ok[r]) {
            win[r] = s_win[r]; kp[r] = s_kp[r];
            int tb = hist[r][win[r]] - hist[r][win[r] + 1];
            sel[r] = (tb <= 64);
        } else { sel[r] = false; win[r] = 0; kp[r] = 0; }
    }

    // direct emit + threshold-bin collection (both rows)
#pragma unroll
    for (int r = 0; r < 2; r++) {
        if (sel[r]) {
            int* op = g_idx + (rbase + r) * Kn;
#pragma unroll
            for (int i = 0; i < 8; i++) {
                if (bin[r][i] > win[r]) {
                    op[atomicAdd(&s_cnt[r], 1)] = tid * 8 + i;
                } else if (bin[r][i] == win[r]) {
                    int q = atomicAdd(&s_tb[r], 1);
                    cv[r][q] = f[r][i]; cix[r][q] = (unsigned short)(tid * 8 + i);
                }
            }
        }
    }
    __syncthreads();

    // exact rank within threshold bins (cc ~ 1-3 per row)
#pragma unroll
    for (int r = 0; r < 2; r++) {
        if (sel[r]) {
            int cc = s_tb[r], base = s_cnt[r];   // base == Kn - kp[r]
            int* op = g_idx + (rbase + r) * Kn;
            for (int i = tid; i < cc; i += 256) {
                float vi = cv[r][i]; int xi = cix[r][i];
                int rk = 0;
                for (int j = 0; j < cc; j++) {
                    float vj = cv[r][j];
                    rk += (vj > vi) || (vj == vi && cix[r][j] < xi);
                }
                if (rk < kp[r]) op[base + rk] = xi;
            }
        }
    }

    // exact fallback for rows that didn't take the fast path (block-uniform)
#pragma unroll
    for (int r = 0; r < 2; r++) {
        if (!sel[r]) {                           // sel[r] is block-uniform
            __syncthreads();
            int* op = g_idx + (rbase + r) * Kn;
            float g[8];
#pragma unroll
            for (int i = 0; i < 8; i++) g[i] = f[r][i];
            for (int k = 0; k < Kn; k++) {
                float bv = -FLT_MAX;
                int   bi = 0x7fffffff;
#pragma unroll
                for (int i = 0; i < 8; i++) {
                    int e = tid * 8 + i;
                    if (g[i] > bv) { bv = g[i]; bi = e; }   // i asc -> smallest e on tie
                }
#pragma unroll
                for (int off = 16; off; off >>= 1) {
                    float ov = __shfl_down_sync(0xffffffffu, bv, off);
                    int   oi = __shfl_down_sync(0xffffffffu, bi, off);
                    if (ov > bv || (ov == bv && oi < bi)) { bv = ov; bi = oi; }
                }
                if (lane == 0) { sv[warp] = bv; si[warp] = bi; }
                __syncthreads();
                if (tid == 0) {
                    float fv = sv[0]; int fi = si[0];
#pragma unroll
                    for (int w = 1; w < 8; w++)
                        if (sv[w] > fv || (sv[w] == fv && si[w] < fi)) { fv = sv[w]; fi = si[w]; }
                    swin = fi;
                    op[k] = fi;
                }
                __syncthreads();
                int w = swin;
                if ((w >> 3) == tid) g[w & 7] = -FLT_MAX;
            }
        }
    }
}

// ---------------- kernel 4: U = Wd.x , Bse = (Wc-Wd).x  (o-contiguous layout) -----------
__global__ void k_uv(const float* __restrict__ x, const float* __restrict__ W) {
    int b = blockIdx.y;
    int m0 = blockIdx.x * 64;
    __shared__ float Wd[64 * 64];   // [c][o]
    __shared__ float Wf[64 * 64];   // [c][o]  (Wc - Wd)
    __shared__ float xs[64 * 64];   // [c][m]
    int tid = threadIdx.x;
#pragma unroll
    for (int i = 0; i < 16; i++) {
        int id = tid + 256 * i;
        int o = id >> 6, c = id & 63;
        float wd = W[o * 128 + c];
        float wc = W[o * 128 + 64 + c];
        Wd[c * 64 + o] = wd;
        Wf[c * 64 + o] = wc - wd;
        xs[id] = x[(size_t)b * Cn * Nn + (size_t)(id >> 6) * Nn + m0 + (id & 63)];
    }
    __syncthreads();

    int o = tid & 63, mq = tid >> 6;
    float aU[16], aD[16];
#pragma unroll
    for (int t = 0; t < 16; t++) { aU[t] = 0.f; aD[t] = 0.f; }

    for (int c = 0; c < 64; c++) {
        float wu = Wd[c * 64 + o];
        float wf = Wf[c * 64 + o];
#pragma unroll
        for (int t = 0; t < 16; t++) {
            float xv = xs[c * 64 + mq + t * 4];   // broadcast within warp
            aU[t] = fmaf(wu, xv, aU[t]);
            aD[t] = fmaf(wf, xv, aD[t]);
        }
    }
#pragma unroll
    for (int t = 0; t < 16; t++) {
        int m = m0 + mq + t * 4;
        g_U  [((size_t)b * Nn + m) * On + o] = aU[t];
        g_Bse[((size_t)b * Nn + m) * On + o] = aD[t];
    }
}

// ---------------- kernel 5: per-channel sum / sumsq of y over (b,n,k) ----------------
__global__ void k_stats() {
    int b = blockIdx.y;
    int n0 = blockIdx.x * 128;
    int tid = threadIdx.x;
    int o = tid & 63, g = tid >> 6;
    float s = 0.f, s2 = 0.f;
    for (int j = 0; j < 32; j++) {
        int n = n0 + g * 32 + j;
        float bse = g_Bse[((size_t)b * Nn + n) * On + o];
        const int* ip = g_idx + (b * Nn + n) * Kn;
#pragma unroll
        for (int k = 0; k < Kn; k++) {
            int m = ip[k];
            float y = g_U[((size_t)b * Nn + m) * On + o] + bse;
            s += y;
            s2 = fmaf(y, y, s2);
        }
    }
    __shared__ float ss[4][64], ss2[4][64];
    ss[g][o] = s; ss2[g][o] = s2;
    __syncthreads();
    if (g == 0) {
        double ts = (double)ss[0][o] + (double)ss[1][o] + (double)ss[2][o] + (double)ss[3][o];
        double t2 = (double)ss2[0][o] + (double)ss2[1][o] + (double)ss2[2][o] + (double)ss2[3][o];
        atomicAdd(&g_sum[o], ts);
        atomicAdd(&g_sumsq[o], t2);
    }
}

// ---------------- kernel 6: finalize BN affine ----------------
__global__ void k_fin(const float* __restrict__ gamma, const float* __restrict__ beta) {
    int o = threadIdx.x;
    double mean = g_sum[o] / (double)CNT_TOT;
    double var  = g_sumsq[o] / (double)CNT_TOT - mean * mean;
    float sc = gamma[o] * rsqrtf((float)var + 1e-5f);
    g_scale[o] = sc;
    g_shift[o] = beta[o] - (float)mean * sc;
}

// ---------------- kernel 7: normalize + leaky relu + max over k -> out[b][o][n] --------
__global__ void k_out(float* __restrict__ out) {
    int b = blockIdx.y;
    int n0 = blockIdx.x * 32;
    int tid = threadIdx.x;
    int o = tid & 63, nq = tid >> 6;
    __shared__ float sm[64 * 33];
    float sc = g_scale[o], sh = g_shift[o];
    for (int j = 0; j < 8; j++) {
        int nl = nq * 8 + j;
        int n = n0 + nl;
        float bse = g_Bse[((size_t)b * Nn + n) * On + o];
        const int* ip = g_idx + (b * Nn + n) * Kn;
        float mx = -FLT_MAX;
#pragma unroll
        for (int k = 0; k < Kn; k++) {
            int m = ip[k];
            float y  = g_U[((size_t)b * Nn + m) * On + o] + bse;
            float yn = fmaf(y, sc, sh);
            float a  = (yn >= 0.f) ? yn : 0.2f * yn;
            mx = fmaxf(mx, a);
        }
        sm[o * 33 + nl] = mx;
    }
    __syncthreads();
    int nl2 = tid & 31, og = tid >> 5;
#pragma unroll
    for (int j = 0; j < 8; j++) {
        int o2 = og * 8 + j;
        out[((size_t)b * On + o2) * Nn + n0 + nl2] = sm[o2 * 33 + nl2];
    }
}

// ---------------- launch ----------------
extern "C" void kernel_launch(void* const* d_in, const int* in_sizes, int n_in,
                              void* d_out, int out_size) {
    const float* x     = (const float*)d_in[0];
    const float* W     = (const float*)d_in[1];
    const float* gamma = (const float*)d_in[2];
    const float* beta  = (const float*)d_in[3];
    float* out = (float*)d_out;

    k_zero<<<1, 64>>>();
    k_xx<<<(Bn * Nn) / 256, 256>>>(x);

    dim3 gg(136, 16);                 // triangular tile set, 128x128 tiles
    k_gram<<<gg, 256>>>(x);

    k_topk2<<<(Bn * Nn) / 2, 256>>>();

    dim3 guv(Nn / 64, Bn);
    k_uv<<<guv, 256>>>(x, W);

    dim3 gst(16, Bn);
    k_stats<<<gst, 256>>>();

    k_fin<<<1, 64>>>(gamma, beta);

    dim3 go(Nn / 32, Bn);
    k_out<<<go, 256>>>(out);
}